// round 2
// baseline (speedup 1.0000x reference)
#include <cuda_runtime.h>
#include <cstdint>

// CRF NLL: B=256, L=512, T=32 (START=30, STOP=31).
// Per batch b (one warp, thread j = tag j):
//   q_j = log2-domain partition value.
//   step: e_i = 2^(q_i - M);  dot_j = sum_i E[i][j] * e_i  (E = exp(trans), in regs)
//         q_j' = feats*log2e + M + log2(dot_j)
//   M is a stale broadcast of q[lane16] (exact power-of-2 scaling => no precision loss).
// Gold path score computed by the same warp (strided over l).
// result_b = ln2*(M + log2(dot_STOP)) - gold_b ; kernel2 reduces 256 -> scalar.
//
// mask dtype is detected at runtime (bool may land as int32 / uint8 / float32):
// mask[0,0] is guaranteed true (lengths >= 256), so word0 of the buffer
// disambiguates: 1 -> int32, 0x01010101 -> uint8, 0x3F800000 -> float32.

static constexpr int Bn = 256;
static constexpr int Ln = 512;
static constexpr int Tn = 32;
static constexpr int T_START = 30;
static constexpr int T_STOP  = 31;
static constexpr int WPB = 4;  // warps (batches) per block

#define FULLMASK 0xffffffffu
#define LOG2E_F 1.4426950408889634f
#define LN2_F   0.6931471805599453f

__device__ float g_res[Bn];

__device__ __forceinline__ float ex2f_(float x) {
    float y; asm("ex2.approx.f32 %0, %1;" : "=f"(y) : "f"(x)); return y;
}
__device__ __forceinline__ float lg2f_(float x) {
    float y; asm("lg2.approx.f32 %0, %1;" : "=f"(y) : "f"(x)); return y;
}
__device__ __forceinline__ unsigned long long fma2_(unsigned long long a,
                                                    unsigned long long b,
                                                    unsigned long long c) {
    unsigned long long d;
    asm("fma.rn.f32x2 %0, %1, %2, %3;" : "=l"(d) : "l"(a), "l"(b), "l"(c));
    return d;
}
__device__ __forceinline__ unsigned long long pack2_(float lo, float hi) {
    unsigned long long d;
    asm("mov.b64 %0, {%1, %2};" : "=l"(d)
        : "r"(__float_as_uint(lo)), "r"(__float_as_uint(hi)));
    return d;
}
__device__ __forceinline__ void unpack2_(unsigned long long v, float& lo, float& hi) {
    unsigned a, b;
    asm("mov.b64 {%0, %1}, %2;" : "=r"(a), "=r"(b) : "l"(v));
    lo = __uint_as_float(a); hi = __uint_as_float(b);
}

__global__ void __launch_bounds__(WPB * 32, 1)
crf_forward_kernel(const float* __restrict__ feats,
                   const void* __restrict__ maskp,
                   const int* __restrict__ tags,
                   const float* __restrict__ trans) {
    __shared__ __align__(16) float sm_e[WPB][2][Tn];

    const int warp = threadIdx.x >> 5;
    const int lane = threadIdx.x & 31;
    const int b = blockIdx.x * WPB + warp;

    const float* __restrict__ fb = feats + (size_t)b * (Ln * Tn);
    const int* __restrict__ tb = tags + (size_t)b * Ln;

    // ---- sequence length: mask is a contiguous true-prefix; dtype detected ----
    const unsigned w0 = ((const unsigned*)maskp)[0];  // mask[0,0] is true
    int cnt = 0;
    if (w0 == 1u) {                       // bool stored as int32
        const int* mb = (const int*)maskp + (size_t)b * Ln;
        #pragma unroll 4
        for (int l = lane; l < Ln; l += 32) cnt += (mb[l] != 0);
    } else if (w0 == 0x3F800000u) {       // bool stored as float32
        const float* mb = (const float*)maskp + (size_t)b * Ln;
        #pragma unroll 4
        for (int l = lane; l < Ln; l += 32) cnt += (mb[l] != 0.0f);
    } else {                              // bool stored as uint8/int8
        const unsigned char* mb = (const unsigned char*)maskp + (size_t)b * Ln;
        #pragma unroll 4
        for (int l = lane; l < Ln; l += 32) cnt += (mb[l] != 0);
    }
    const int len = __reduce_add_sync(FULLMASK, cnt);

    // ---- gold path score (strided over l, warp-reduced) ----
    float gold = 0.0f;
    for (int l = lane; l < len; l += 32) {
        int t = tb[l];
        int prev = (l == 0) ? T_START : tb[l - 1];
        gold += fb[l * Tn + t] + trans[prev * Tn + t];
    }
    #pragma unroll
    for (int o = 16; o; o >>= 1) gold += __shfl_xor_sync(FULLMASK, gold, o);
    gold += trans[tb[len - 1] * Tn + T_STOP];  // end energy (all lanes same)

    // ---- E column for this thread's tag j = lane: E[i] = exp(trans[i][lane]) ----
    unsigned long long E2[Tn / 2];
    #pragma unroll
    for (int i = 0; i < Tn / 2; i++) {
        float e0 = ex2f_(trans[(2 * i) * Tn + lane] * LOG2E_F);
        float e1 = ex2f_(trans[(2 * i + 1) * Tn + lane] * LOG2E_F);
        E2[i] = pack2_(e0, e1);
    }

    // ---- init: q_j = (feats[b,0,j] + trans[START,j]) * log2(e) ----
    float q = (fb[lane] + trans[T_START * Tn + lane]) * LOG2E_F;
    float Mst = __shfl_sync(FULLMASK, q, 16);  // lane 16 is a live tag

    // feats prefetch pipeline (2 deep; L2 latency ~260cyc > 1 iter)
    float fA = fb[1 * Tn + lane];
    float fB = fb[2 * Tn + lane];

    int buf = 0;
    for (int l = 1; l < len; ++l) {
        float e = ex2f_(q - Mst);
        sm_e[warp][buf][lane] = e;

        float Mnext = __shfl_sync(FULLMASK, q, 16);  // stale M for next iter (off-chain)
        float fcur = fA; fA = fB;
        int lpre = l + 2; if (lpre > Ln - 1) lpre = Ln - 1;
        fB = fb[lpre * Tn + lane];

        __syncwarp();

        const longlong2* sv = reinterpret_cast<const longlong2*>(&sm_e[warp][buf][0]);
        unsigned long long a0 = 0ull, a1 = 0ull;  // packed (0,0)
        #pragma unroll
        for (int k = 0; k < 8; k++) {
            longlong2 v = sv[k];  // one LDS.128 broadcast: e[4k..4k+3]
            a0 = fma2_(E2[2 * k],     (unsigned long long)v.x, a0);
            a1 = fma2_(E2[2 * k + 1], (unsigned long long)v.y, a1);
        }
        float x0, x1, y0, y1;
        unpack2_(a0, x0, x1);
        unpack2_(a1, y0, y1);
        float dot = (x0 + x1) + (y0 + y1);

        q = fmaf(fcur, LOG2E_F, Mst + lg2f_(dot));
        Mst = Mnext;
        buf ^= 1;
    }

    // ---- final: lse over i of (trans[i,STOP] + p_i); thread STOP owns column STOP ----
    float e = ex2f_(q - Mst);
    sm_e[warp][buf][lane] = e;
    __syncwarp();
    if (lane == T_STOP) {
        const longlong2* sv = reinterpret_cast<const longlong2*>(&sm_e[warp][buf][0]);
        unsigned long long a0 = 0ull, a1 = 0ull;
        #pragma unroll
        for (int k = 0; k < 8; k++) {
            longlong2 v = sv[k];
            a0 = fma2_(E2[2 * k],     (unsigned long long)v.x, a0);
            a1 = fma2_(E2[2 * k + 1], (unsigned long long)v.y, a1);
        }
        float x0, x1, y0, y1;
        unpack2_(a0, x0, x1);
        unpack2_(a1, y0, y1);
        float dot = (x0 + x1) + (y0 + y1);
        float fwd = (Mst + lg2f_(dot)) * LN2_F;
        g_res[b] = fwd - gold;
    }
}

__global__ void crf_reduce_kernel(float* __restrict__ out) {
    __shared__ float s[8];
    int t = threadIdx.x;
    float v = g_res[t];
    #pragma unroll
    for (int o = 16; o; o >>= 1) v += __shfl_xor_sync(FULLMASK, v, o);
    if ((t & 31) == 0) s[t >> 5] = v;
    __syncthreads();
    if (t < 32) {
        float w = (t < 8) ? s[t] : 0.0f;
        #pragma unroll
        for (int o = 4; o; o >>= 1) w += __shfl_xor_sync(FULLMASK, w, o);
        if (t == 0) out[0] = w;
    }
}

extern "C" void kernel_launch(void* const* d_in, const int* in_sizes, int n_in,
                              void* d_out, int out_size) {
    const float* feats = (const float*)d_in[0];
    const void* mask = (const void*)d_in[1];
    const int* tags = (const int*)d_in[2];
    const float* trans = (const float*)d_in[3];

    crf_forward_kernel<<<Bn / WPB, WPB * 32>>>(feats, mask, tags, trans);
    crf_reduce_kernel<<<1, 256>>>((float*)d_out);
}

// round 3
// speedup vs baseline: 1.3356x; 1.3356x over previous
#include <cuda_runtime.h>
#include <cstdint>

// CRF NLL, linear-domain scaled forward algorithm.
// B=256, L=512, T=32 (START=30, STOP=31). One warp per batch, thread j = tag j.
//   alpha'_j = g_j * s * sum_i E[i][j] * alpha_i
//     E = exp(trans) held in registers (packed f32x2 column per thread),
//     g_j = exp(feats[t,j]) computed one step ahead (off critical chain),
//     s = 2^{-k} exact power-of-2 rescale, k from exponent field of a shfl'd
//         alpha (also off-chain); K accumulates k.
//   forward_b = ln2 * (log2(dot(E[:,STOP], alpha_final)) + K)
// Gold path score computed by the same warp (strided over l).
// Reduction fused via deterministic last-block pattern.

static constexpr int Bn = 256;
static constexpr int Ln = 512;
static constexpr int Tn = 32;
static constexpr int T_START = 30;
static constexpr int T_STOP  = 31;
static constexpr int WPB = 4;              // warps (batches) per block
static constexpr int NBLK = Bn / WPB;      // 64 blocks

#define FULLMASK 0xffffffffu
#define LOG2E_F 1.4426950408889634f
#define LN2_F   0.6931471805599453f

typedef unsigned long long ull;

__device__ float g_res[Bn];
__device__ int g_cnt = 0;

__device__ __forceinline__ float ex2f_(float x) {
    float y; asm("ex2.approx.f32 %0, %1;" : "=f"(y) : "f"(x)); return y;
}
__device__ __forceinline__ float lg2f_(float x) {
    float y; asm("lg2.approx.f32 %0, %1;" : "=f"(y) : "f"(x)); return y;
}
__device__ __forceinline__ ull fma2_(ull a, ull b, ull c) {
    ull d; asm("fma.rn.f32x2 %0, %1, %2, %3;" : "=l"(d) : "l"(a), "l"(b), "l"(c));
    return d;
}
__device__ __forceinline__ ull mul2_(ull a, ull b) {
    ull d; asm("mul.rn.f32x2 %0, %1, %2;" : "=l"(d) : "l"(a), "l"(b));
    return d;
}
__device__ __forceinline__ ull add2_(ull a, ull b) {
    ull d; asm("add.rn.f32x2 %0, %1, %2;" : "=l"(d) : "l"(a), "l"(b));
    return d;
}
__device__ __forceinline__ ull pack2_(float lo, float hi) {
    ull d;
    asm("mov.b64 %0, {%1, %2};" : "=l"(d)
        : "r"(__float_as_uint(lo)), "r"(__float_as_uint(hi)));
    return d;
}
__device__ __forceinline__ void unpack2_(ull v, float& lo, float& hi) {
    unsigned a, b;
    asm("mov.b64 {%0, %1}, %2;" : "=r"(a), "=r"(b) : "l"(v));
    lo = __uint_as_float(a); hi = __uint_as_float(b);
}

__global__ void __launch_bounds__(WPB * 32, 1)
crf_kernel(const float* __restrict__ feats,
           const void* __restrict__ maskp,
           const int* __restrict__ tags,
           const float* __restrict__ trans,
           float* __restrict__ out) {
    __shared__ __align__(16) float sm_e[WPB][2][Tn];
    __shared__ float red[WPB];
    __shared__ int isLast;

    const int warp = threadIdx.x >> 5;
    const int lane = threadIdx.x & 31;
    const int b = blockIdx.x * WPB + warp;

    const float* __restrict__ fb = feats + (size_t)b * (Ln * Tn);
    const int* __restrict__ tb = tags + (size_t)b * Ln;

    // ---- sequence length: mask is a contiguous true-prefix; dtype detected ----
    const unsigned w0 = ((const unsigned*)maskp)[0];  // mask[0,0] is true
    int cnt = 0;
    if (w0 == 1u) {                       // bool stored as int32
        const int* mb = (const int*)maskp + (size_t)b * Ln;
        #pragma unroll 4
        for (int l = lane; l < Ln; l += 32) cnt += (mb[l] != 0);
    } else if (w0 == 0x3F800000u) {       // bool stored as float32
        const float* mb = (const float*)maskp + (size_t)b * Ln;
        #pragma unroll 4
        for (int l = lane; l < Ln; l += 32) cnt += (mb[l] != 0.0f);
    } else {                              // bool stored as uint8/int8
        const unsigned char* mb = (const unsigned char*)maskp + (size_t)b * Ln;
        #pragma unroll 4
        for (int l = lane; l < Ln; l += 32) cnt += (mb[l] != 0);
    }
    const int len = __reduce_add_sync(FULLMASK, cnt);

    // ---- gold path score (strided over l, warp-reduced) ----
    float gold = 0.0f;
    for (int l = lane; l < len; l += 32) {
        int t = tb[l];
        int prev = (l == 0) ? T_START : tb[l - 1];
        gold += fb[l * Tn + t] + trans[prev * Tn + t];
    }
    #pragma unroll
    for (int o = 16; o; o >>= 1) gold += __shfl_xor_sync(FULLMASK, gold, o);
    gold += trans[tb[len - 1] * Tn + T_STOP];  // end energy (all lanes same)

    // ---- E column for tag j = lane: E2[i] = {exp(trans[2i][j]), exp(trans[2i+1][j])} ----
    ull E2[Tn / 2];
    #pragma unroll
    for (int i = 0; i < Tn / 2; i++) {
        float e0 = ex2f_(trans[(2 * i) * Tn + lane] * LOG2E_F);
        float e1 = ex2f_(trans[(2 * i + 1) * Tn + lane] * LOG2E_F);
        E2[i] = pack2_(e0, e1);
    }

    // ---- init: alpha_j = exp(feats[0,j] + trans[START,j]), K = 0 ----
    float A = ex2f_((fb[lane] + trans[T_START * Tn + lane]) * LOG2E_F);
    int K = 0;
    sm_e[warp][0][lane] = A;

    // scale + g for step 1 (off-chain style, but prologue so just compute)
    unsigned bits = __shfl_sync(FULLMASK, __float_as_uint(A), 16);
    int ef = (int)(bits >> 23);
    K += ef - 127;
    float s = __uint_as_float((unsigned)(254 - ef) << 23);
    float gcur = ex2f_(fb[1 * Tn + lane] * LOG2E_F) * s;

    // feats prefetch queue, 3 deep: fq0=f[l+1], fq1=f[l+2], fq2=f[l+3] at iter l
    float fq0 = fb[2 * Tn + lane];
    float fq1 = fb[3 * Tn + lane];
    float fq2 = fb[4 * Tn + lane];
    __syncwarp();

#define CRF_STEP(SRC, DST, L)                                                  \
    do {                                                                       \
        const longlong2* sv =                                                  \
            reinterpret_cast<const longlong2*>(&sm_e[warp][SRC][0]);           \
        longlong2 v0 = sv[0], v1 = sv[1], v2 = sv[2], v3 = sv[3];              \
        longlong2 v4 = sv[4], v5 = sv[5], v6 = sv[6], v7 = sv[7];              \
        ull a0 = mul2_(E2[0], (ull)v0.x);                                      \
        ull a1 = mul2_(E2[1], (ull)v0.y);                                      \
        ull a2 = mul2_(E2[2], (ull)v1.x);                                      \
        ull a3 = mul2_(E2[3], (ull)v1.y);                                      \
        a0 = fma2_(E2[4], (ull)v2.x, a0);                                      \
        a1 = fma2_(E2[5], (ull)v2.y, a1);                                      \
        a2 = fma2_(E2[6], (ull)v3.x, a2);                                      \
        a3 = fma2_(E2[7], (ull)v3.y, a3);                                      \
        a0 = fma2_(E2[8], (ull)v4.x, a0);                                      \
        a1 = fma2_(E2[9], (ull)v4.y, a1);                                      \
        a2 = fma2_(E2[10], (ull)v5.x, a2);                                     \
        a3 = fma2_(E2[11], (ull)v5.y, a3);                                     \
        a0 = fma2_(E2[12], (ull)v6.x, a0);                                     \
        a1 = fma2_(E2[13], (ull)v6.y, a1);                                     \
        a2 = fma2_(E2[14], (ull)v7.x, a2);                                     \
        a3 = fma2_(E2[15], (ull)v7.y, a3);                                     \
        ull s01 = add2_(a0, a1);                                               \
        ull s23 = add2_(a2, a3);                                               \
        ull st = add2_(s01, s23);                                              \
        float lo, hi;                                                          \
        unpack2_(st, lo, hi);                                                  \
        float Anew = (lo + hi) * gcur;                                         \
        sm_e[warp][DST][lane] = Anew;                                          \
        unsigned bts = __shfl_sync(FULLMASK, __float_as_uint(Anew), 16);       \
        int e_ = (int)(bts >> 23);                                             \
        K += e_ - 127;                                                         \
        float s_ = __uint_as_float((unsigned)(254 - e_) << 23);                \
        float gnext = ex2f_(fq0 * LOG2E_F) * s_;                               \
        fq0 = fq1; fq1 = fq2;                                                  \
        {                                                                      \
            int lp = (L) + 4;                                                  \
            if (lp > Ln - 1) lp = Ln - 1;                                      \
            fq2 = fb[lp * Tn + lane];                                          \
        }                                                                      \
        __syncwarp();                                                          \
        gcur = gnext;                                                          \
    } while (0)

    int l = 1;
    for (; l + 1 < len; l += 2) {
        CRF_STEP(0, 1, l);
        CRF_STEP(1, 0, l + 1);
    }
    if (l < len) {
        CRF_STEP(0, 1, l);
    }
    const int fbuf = (len - 1) & 1;

    // ---- final: dot with E column STOP (owned by lane STOP) ----
    if (lane == T_STOP) {
        const longlong2* sv = reinterpret_cast<const longlong2*>(&sm_e[warp][fbuf][0]);
        ull a0 = 0ull, a1 = 0ull;
        #pragma unroll
        for (int k2 = 0; k2 < 8; k2++) {
            longlong2 v = sv[k2];
            a0 = fma2_(E2[2 * k2], (ull)v.x, a0);
            a1 = fma2_(E2[2 * k2 + 1], (ull)v.y, a1);
        }
        float x0, x1, y0, y1;
        unpack2_(a0, x0, x1);
        unpack2_(a1, y0, y1);
        float dot = (x0 + x1) + (y0 + y1);
        float fwd = (lg2f_(dot) + (float)K) * LN2_F;
        g_res[b] = fwd - gold;
    }

    // ---- deterministic last-block reduction (256 -> scalar) ----
    __syncthreads();
    if (threadIdx.x == 0) {
        __threadfence();
        int old = atomicAdd(&g_cnt, 1);
        isLast = (old == NBLK - 1) ? 1 : 0;
    }
    __syncthreads();
    if (isLast) {
        __threadfence();
        int t = threadIdx.x;  // 0..127
        float v = g_res[t] + g_res[t + 128];
        #pragma unroll
        for (int o = 16; o; o >>= 1) v += __shfl_xor_sync(FULLMASK, v, o);
        if ((t & 31) == 0) red[t >> 5] = v;
        __syncthreads();
        if (t == 0) {
            out[0] = (red[0] + red[1]) + (red[2] + red[3]);
            g_cnt = 0;  // reset for graph replay
        }
    }
}

extern "C" void kernel_launch(void* const* d_in, const int* in_sizes, int n_in,
                              void* d_out, int out_size) {
    const float* feats = (const float*)d_in[0];
    const void* mask = (const void*)d_in[1];
    const int* tags = (const int*)d_in[2];
    const float* trans = (const float*)d_in[3];

    crf_kernel<<<NBLK, WPB * 32>>>(feats, mask, tags, trans, (float*)d_out);
}